// round 12
// baseline (speedup 1.0000x reference)
#include <cuda_runtime.h>
#include <cstdint>

#define B_ 8
#define V_ 8192
#define N_ 2048
#define C_ 128
#define GRID_ 128
#define THR_ 1024

typedef unsigned long long ull;

// ---------- f32x2 helpers (sm_100+ packed fp32) ----------
__device__ __forceinline__ ull pk2(float lo, float hi) {
    ull r; asm("mov.b64 %0, {%1, %2};" : "=l"(r) : "f"(lo), "f"(hi)); return r;
}
__device__ __forceinline__ void upk2(ull v, float& lo, float& hi) {
    asm("mov.b64 {%0, %1}, %2;" : "=f"(lo), "=f"(hi) : "l"(v));
}
__device__ __forceinline__ ull ffma2(ull a, ull b, ull c) {
    ull d; asm("fma.rn.f32x2 %0, %1, %2, %3;" : "=l"(d) : "l"(a), "l"(b), "l"(c)); return d;
}

// ---------- device scratch ----------
__device__ float g_buf[B_ * N_];
__device__ unsigned int bar1, bar_done;

// =====================================================================
// ONE persistent kernel, grid=128 (1 CTA/SM), 1024 threads (32 warps,
// occ 50% vs prior 25%), 96KB dyn smem, hard 64-reg cap (re-tiled fit).
//
// Phase 1: g table. Warp = 4 rows x 64 outputs; thread = 4 rows x 2 d
//   (acc[4][2] = 16 regs). W pairs in plain d-order; thread's 2 pairs =
//   one LDS.128 @16B lane stride (4 wf = crossbar minimum for 512B).
//   -> t0 ARRIVES on grid barrier; nobody waits yet.
// Phase 2: screening: thread = 256-pt slice x Q=4 verts; two independent
//   running-min chains per q (same min value, more ILP); best-2 segs
//   per (vert,slice) -> 16 entries -> lex combine -> exact
//   reference-rounding rescan (wide LDS.128) -> barrier WAIT -> gather.
// =====================================================================
__global__ void __launch_bounds__(THR_, 1)
kernelFused(const float* __restrict__ verts,
            const float* __restrict__ gpos,
            const float* __restrict__ processed,
            const float* __restrict__ W1,
            const float* __restrict__ b1,
            const float* __restrict__ W2,
            const float* __restrict__ b2,
            float* __restrict__ out) {
    extern __shared__ char sm[];
    // phase1 overlay
    ull*   Ws = (ull*)sm;                     // 64KB: Ws[c2*128+d] = {W1[2c2][d],W1[2c2+1][d]}
    float* Xs = (float*)(sm + 65536);         // 32KB X tile
    // phase2 overlay
    float* pts  = (float*)sm;                 // 32KB pair-packed points
    float* cval = (float*)(sm + 32768);       // 16 x 512 floats = 32KB
    int*   cseg = (int*)(sm + 65536);         // 16 x 512 ints   = 32KB
    __shared__ float red[64][65];

    const int t   = threadIdx.x;
    const int bid = blockIdx.x;

    // ---------------- Phase 1: g table ----------------
#pragma unroll
    for (int k = 0; k < 8; k++) {
        int i = t + k * THR_;                 // 0..8191
        int c2 = i >> 7, d = i & 127;
        Ws[i] = pk2(W1[(2 * c2) * C_ + d], W1[(2 * c2 + 1) * C_ + d]);
    }

    const int w    = t >> 5;
    const int lane = t & 31;
    const int rg   = w >> 1;                  // 0..15 row-groups
    const int dh   = w & 1;                   // d-half
    const int r0   = rg * 4;                  // 4 rows
    const int d0   = dh * 64 + lane * 2;      // 2 outputs: d0, d0+1

#pragma unroll 1
    for (int h = 0; h < 2; h++) {
        const int rb = bid * 128 + h * 64;

        const float4* src = (const float4*)(processed + (size_t)rb * C_);
        float4* dst = (float4*)Xs;
        dst[t] = src[t];
        dst[t + THR_] = src[t + THR_];
        __syncthreads();

        ull acc[4][2];
#pragma unroll
        for (int i = 0; i < 4; i++) { acc[i][0] = 0ull; acc[i][1] = 0ull; }

#pragma unroll 4
        for (int c4 = 0; c4 < 32; c4++) {     // two c2 per step
            ulonglong2 xv[4];
#pragma unroll
            for (int i = 0; i < 4; i++)
                xv[i] = *(const ulonglong2*)&Xs[(r0 + i) * 128 + 4 * c4];  // uniform
#pragma unroll
            for (int half = 0; half < 2; half++) {
                const int c2 = 2 * c4 + half;
                ulonglong2 wv = *(const ulonglong2*)&Ws[c2 * 128 + d0];    // 4 wf (min)
#pragma unroll
                for (int i = 0; i < 4; i++) {
                    ull xi = half ? xv[i].y : xv[i].x;
                    acc[i][0] = ffma2(xi, wv.x, acc[i][0]);
                    acc[i][1] = ffma2(xi, wv.y, acc[i][1]);
                }
            }
        }

        // Epilogue: 2 outputs per thread -> partial dot with W2
        float b10 = b1[d0], b11 = b1[d0 + 1];
        float w20 = W2[d0], w21 = W2[d0 + 1];
#pragma unroll
        for (int i = 0; i < 4; i++) {
            float lo, hi, l2, h2;
            upk2(acc[i][0], lo, hi);
            upk2(acc[i][1], l2, h2);
            float h0 = fmaxf(lo + hi + b10, 0.f);
            float h1 = fmaxf(l2 + h2 + b11, 0.f);
            red[r0 + i][dh * 32 + lane] = fmaf(h1, w21, h0 * w20);
        }
        __syncthreads();

        if (t < 64) {
            float s = b2[0];
#pragma unroll
            for (int k = 0; k < 64; k++) s += red[t][k];
            g_buf[rb + t] = s;
        }
        __syncthreads();
    }

    // ---- Grid barrier ARRIVE only (release g_buf); wait comes later ----
    if (t == 0) {
        __threadfence();
        atomicAdd(&bar1, 1u);
    }

    // ---------------- Phase 2: screening (independent of g_buf) ----------------
    const int vc = bid & 15;
    const int b  = bid >> 4;
    const int v0 = vc * 512;

    // Pair-packed full-N tile: pair j -> {x0,x1,y0,y1}{z0,z1,pp0,pp1}
    {
        int j = t;                            // exactly 1024 pairs
        const float* p0 = gpos + ((size_t)b * N_ + 2 * j) * 3;
        float x0 = p0[0], y0 = p0[1], z0 = p0[2];
        float x1 = p0[3], y1 = p0[4], z1 = p0[5];
        float pp0 = __fmaf_rn(z0, z0, __fmaf_rn(y0, y0, __fmul_rn(x0, x0)));
        float pp1 = __fmaf_rn(z1, z1, __fmaf_rn(y1, y1, __fmul_rn(x1, x1)));
        float4* d = (float4*)&pts[j * 8];
        d[0] = make_float4(x0, x1, y0, y1);
        d[1] = make_float4(z0, z1, pp0, pp1);
    }
    __syncthreads();

    // Thread: slice ns (256 points), 4 verts (vg + q*128)
    const int ns = t >> 7;      // 0..7 (constant within a warp)
    const int vg = t & 127;

    ull VX[4], VY[4], VZ[4];    // splatted -2*v : 24 regs
#pragma unroll
    for (int q = 0; q < 4; q++) {
        const float* vp = verts + ((size_t)b * V_ + v0 + vg + q * 128) * 3;
        float x = -2.f * vp[0], y = -2.f * vp[1], z = -2.f * vp[2];
        VX[q] = pk2(x, x); VY[q] = pk2(y, y); VZ[q] = pk2(z, z);
    }

    const float INF = __int_as_float(0x7f800000);
    float best[4], sec[4];
    int sgpk[4];                // bits0-7 sgA, bits8-15 sgB (local 0..7)
#pragma unroll
    for (int q = 0; q < 4; q++) { best[q] = INF; sec[q] = INF; sgpk[q] = 0; }

    // 8 segments of 32 points (16 pairs) within this slice
#pragma unroll 1
    for (int s = 0; s < 8; s++) {
        float mlo[4], mhi[4];
#pragma unroll
        for (int q = 0; q < 4; q++) { mlo[q] = INF; mhi[q] = INF; }
        const ulonglong2* base = (const ulonglong2*)&pts[(ns * 128 + s * 16) * 8];
#pragma unroll 4
        for (int k = 0; k < 16; k++) {
            ulonglong2 a  = base[2 * k];       // {x0,x1},{y0,y1}
            ulonglong2 bq = base[2 * k + 1];   // {z0,z1},{pp0,pp1}
#pragma unroll
            for (int q = 0; q < 4; q++) {
                ull sc = ffma2(VZ[q], bq.x,
                          ffma2(VY[q], a.y,
                           ffma2(VX[q], a.x, bq.y)));
                float lo, hi; upk2(sc, lo, hi);
                mlo[q] = fminf(mlo[q], lo);    // two independent chains
                mhi[q] = fminf(mhi[q], hi);
            }
        }
#pragma unroll
        for (int q = 0; q < 4; q++) {
            float m = fminf(mlo[q], mhi[q]);
            int sp = sgpk[q];
            if (m < best[q]) {
                sec[q] = best[q]; sgpk[q] = ((sp & 0xff) << 8) | s;
                best[q] = m;
            } else if (m < sec[q]) {
                sec[q] = m; sgpk[q] = (sp & 0xff) | (s << 8);
            }
        }
    }

    // Write partials, transposed: entry e = ns*2 + {0,1}, vloc = vg + q*128
#pragma unroll
    for (int q = 0; q < 4; q++) {
        int vloc = vg + q * 128;
        int gA = ns * 8 + (sgpk[q] & 0xff);    // global segment 0..63
        int gB = ns * 8 + (sgpk[q] >> 8);
        cval[(ns * 2 + 0) * 512 + vloc] = best[q];
        cseg[(ns * 2 + 0) * 512 + vloc] = gA;
        cval[(ns * 2 + 1) * 512 + vloc] = sec[q];
        cseg[(ns * 2 + 1) * 512 + vloc] = gB;
    }
    __syncthreads();

    // Combine + exact rescan: threads t<512, vertex v0+t.
    int idx = 0;
    if (t < 512) {
        float bv = INF, sv = INF;
        int bs = 64, ss = 64;
#pragma unroll
        for (int e = 0; e < 16; e++) {
            float val = cval[e * 512 + t];     // lanes contiguous: no conflict
            int   sg  = cseg[e * 512 + t];
            bool better = (val < bv) || (val == bv && sg < bs);
            if (better) {
                sv = bv; ss = bs; bv = val; bs = sg;
            } else if ((val < sv) || (val == sv && sg < ss)) {
                sv = val; ss = sg;
            }
        }

        // Exact rescan (reference rounding) of the two segments, ascending.
        const float* vp = verts + ((size_t)b * V_ + v0 + t) * 3;
        float vx = vp[0], vy = vp[1], vz = vp[2];
        float nvx = -2.f * vx, nvy = -2.f * vy, nvz = -2.f * vz;
        float vv = __fmaf_rn(vz, vz, __fmaf_rn(vy, vy, __fmul_rn(vx, vx)));

        int lo = min(bs, ss);
        int hi = max(bs, ss);
        float cur = INF;
#pragma unroll 1
        for (int pass = 0; pass < 2; pass++) {
            if (pass == 1 && hi == lo) break;
            int sb = (pass == 0 ? lo : hi) * 32;
            const ulonglong2* basep = (const ulonglong2*)&pts[(sb >> 1) * 8];
#pragma unroll 1
            for (int j = 0; j < 16; j++) {
                ulonglong2 A  = basep[2 * j];      // {x0,x1},{y0,y1}
                ulonglong2 Bq = basep[2 * j + 1];  // {z0,z1},{pp0,pp1}
                float x0, x1, y0, y1, z0, z1, w0, w1;
                upk2(A.x, x0, x1); upk2(A.y, y0, y1);
                upk2(Bq.x, z0, z1); upk2(Bq.y, w0, w1);
                float s2 = __fmaf_rn(nvz, z0, __fmaf_rn(nvy, y0, __fmul_rn(nvx, x0)));
                float d2 = __fadd_rn(__fadd_rn(vv, s2), w0);
                if (d2 < cur) { cur = d2; idx = sb + 2 * j; }
                float s3 = __fmaf_rn(nvz, z1, __fmaf_rn(nvy, y1, __fmul_rn(nvx, x1)));
                float d3 = __fadd_rn(__fadd_rn(vv, s3), w1);
                if (d3 < cur) { cur = d3; idx = sb + 2 * j + 1; }
            }
        }
    }

    // ---- Grid barrier WAIT (hidden behind screening) ----
    if (t == 0) {
        while (*(volatile unsigned int*)&bar1 < GRID_) __nanosleep(64);
    }
    __syncthreads();
    __threadfence();

    // ---- Gather ----
    if (t < 512) out[b * V_ + v0 + t] = g_buf[b * N_ + idx];

    // ---------------- Exit: reset barrier (last block) ----------------
    __syncthreads();
    if (t == 0) {
        unsigned int r = atomicAdd(&bar_done, 1u);
        if (r == GRID_ - 1) {
            atomicExch(&bar1, 0u);
            atomicExch(&bar_done, 0u);
        }
    }
}

// =====================================================================
extern "C" void kernel_launch(void* const* d_in, const int* in_sizes, int n_in,
                              void* d_out, int out_size) {
    const float* verts = (const float*)d_in[0];   // [8,8192,3]
    const float* gpos  = (const float*)d_in[1];   // [8,2048,3]
    const float* proc  = (const float*)d_in[2];   // [8,2048,128]
    const float* W1    = (const float*)d_in[3];   // [128,128]
    const float* b1    = (const float*)d_in[4];   // [128]
    const float* W2    = (const float*)d_in[5];   // [128,1]
    const float* b2    = (const float*)d_in[6];   // [1]
    float* out = (float*)d_out;                   // [8,8192,1]

    cudaFuncSetAttribute(kernelFused, cudaFuncAttributeMaxDynamicSharedMemorySize,
                         96 * 1024);
    kernelFused<<<GRID_, THR_, 96 * 1024>>>(verts, gpos, proc, W1, b1, W2, b2, out);
}

// round 13
// speedup vs baseline: 1.0300x; 1.0300x over previous
#include <cuda_runtime.h>
#include <cstdint>

#define B_ 8
#define V_ 8192
#define N_ 2048
#define C_ 128
#define GRID_ 128
#define THR_ 512

typedef unsigned long long ull;

// ---------- f32x2 helpers (sm_100+ packed fp32) ----------
__device__ __forceinline__ ull pk2(float lo, float hi) {
    ull r; asm("mov.b64 %0, {%1, %2};" : "=l"(r) : "f"(lo), "f"(hi)); return r;
}
__device__ __forceinline__ void upk2(ull v, float& lo, float& hi) {
    asm("mov.b64 {%0, %1}, %2;" : "=f"(lo), "=f"(hi) : "l"(v));
}
__device__ __forceinline__ ull ffma2(ull a, ull b, ull c) {
    ull d; asm("fma.rn.f32x2 %0, %1, %2, %3;" : "=l"(d) : "l"(a), "l"(b), "l"(c)); return d;
}

// ---------- device scratch ----------
__device__ float g_buf[B_ * N_];
__device__ unsigned int bar1, bar_done;

// =====================================================================
// ONE persistent kernel, grid=128 (1 CTA/SM), 512 threads, 96KB dyn smem.
// WARP-SPECIALIZED: warps 0-7 run the MLP while warps 8-15 run the
// argmin screening CONCURRENTLY (independent work -> stalls of one
// group are filled by issues of the other).
//
//   smem: [0,64K) W packed (MLP)  -> after join: cval/cseg (16KB)
//         [64K,96K) pts pair-packed (alive throughout)
//   MLP (w<8): R11 tiling, 2 row-group passes/warp, X via uniform LDG,
//     W via smem (split-half layout), named barrier 1 for reduction.
//     -> t0 arrives on grid barrier (release g_buf).
//   Screen (w>=8): thread = 4 verts x 1024-pt slice, best-2 segments
//     (of 32 pts) per slice held in REGISTERS across the join.
//   Join (__syncthreads) -> partials to smem -> combine + exact
//   reference-rounding rescan by ALL 512 threads (1 vertex each) ->
//   grid-barrier wait -> gather.
// =====================================================================
__global__ void __launch_bounds__(THR_, 1)
kernelFused(const float* __restrict__ verts,
            const float* __restrict__ gpos,
            const float* __restrict__ processed,
            const float* __restrict__ W1,
            const float* __restrict__ b1,
            const float* __restrict__ W2,
            const float* __restrict__ b2,
            float* __restrict__ out) {
    extern __shared__ char sm[];
    ull*   Ws   = (ull*)sm;                   // 64KB packed W1 (split-half)
    float* cval = (float*)sm;                 // after join: 4 x 512 floats
    int*   cseg = (int*)(sm + 8192);          // after join: 4 x 512 ints
    float* pts  = (float*)(sm + 65536);       // 32KB pair-packed points
    __shared__ float red[64][33];

    const int t   = threadIdx.x;
    const int bid = blockIdx.x;
    const int w   = t >> 5;
    const int lane = t & 31;

    const int vc = bid & 15;
    const int b  = bid >> 4;
    const int v0 = vc * 512;

    // ---------------- Cooperative setup (all 512 threads) ----------------
    // Pack W1 -> smem, split-half layout (R11).
#pragma unroll
    for (int k = 0; k < 16; k++) {
        int i = t + k * THR_;                 // 0..8191
        int c2 = i >> 7;
        int r = i & 127;
        int d = 4 * ((r & 63) >> 1) + (r & 1) + ((r >> 6) << 1);
        Ws[i] = pk2(W1[(2 * c2) * C_ + d], W1[(2 * c2 + 1) * C_ + d]);
    }
    // Pair-packed point tile: pair j -> {x0,x1,y0,y1}{z0,z1,pp0,pp1}
#pragma unroll
    for (int k = 0; k < 2; k++) {
        int j = t + k * THR_;                 // 0..1023
        const float* p0 = gpos + ((size_t)b * N_ + 2 * j) * 3;
        float x0 = p0[0], y0 = p0[1], z0 = p0[2];
        float x1 = p0[3], y1 = p0[4], z1 = p0[5];
        float pp0 = __fmaf_rn(z0, z0, __fmaf_rn(y0, y0, __fmul_rn(x0, x0)));
        float pp1 = __fmaf_rn(z1, z1, __fmaf_rn(y1, y1, __fmul_rn(x1, x1)));
        float4* d = (float4*)&pts[j * 8];
        d[0] = make_float4(x0, x1, y0, y1);
        d[1] = make_float4(z0, z1, pp0, pp1);
    }
    __syncthreads();

    const float INF = __int_as_float(0x7f800000);
    float best[4], sec[4];
    int sgpk[4];

    if (w < 8) {
        // ================= MLP group (threads 0..255) =================
        const int td = lane;                  // 4 outputs: d0 = td*4 (split-half)
        const int d0 = td * 4;
        const ulonglong2* Wsv2 = (const ulonglong2*)Ws;

#pragma unroll 1
        for (int h = 0; h < 2; h++) {
            const int rb = bid * 128 + h * 64;
#pragma unroll 1
            for (int pass = 0; pass < 2; pass++) {
                const int rg = w + pass * 8;  // 0..15
                const int r0 = rg * 4;

                ull acc[4][4];
#pragma unroll
                for (int i = 0; i < 4; i++)
#pragma unroll
                    for (int j = 0; j < 4; j++) acc[i][j] = 0ull;

#pragma unroll 4
                for (int c4 = 0; c4 < 32; c4++) {
                    ulonglong2 xv[4];
#pragma unroll
                    for (int i = 0; i < 4; i++)
                        xv[i] = *(const ulonglong2*)(processed +
                                 (size_t)(rb + r0 + i) * C_ + 4 * c4);  // uniform LDG
#pragma unroll
                    for (int half = 0; half < 2; half++) {
                        const int c2 = 2 * c4 + half;
                        ulonglong2 wa = Wsv2[c2 * 64 + td];        // d = 4td,4td+1
                        ulonglong2 wb = Wsv2[c2 * 64 + 32 + td];   // d = 4td+2,4td+3
                        ull w2[4] = {wa.x, wa.y, wb.x, wb.y};
#pragma unroll
                        for (int i = 0; i < 4; i++) {
                            ull xi = half ? xv[i].y : xv[i].x;
#pragma unroll
                            for (int j = 0; j < 4; j++)
                                acc[i][j] = ffma2(xi, w2[j], acc[i][j]);
                        }
                    }
                }

                float part[4] = {0.f, 0.f, 0.f, 0.f};
#pragma unroll
                for (int j = 0; j < 4; j++) {
                    float b1j = b1[d0 + j];
                    float w2j = W2[d0 + j];
#pragma unroll
                    for (int i = 0; i < 4; i++) {
                        float lo, hi; upk2(acc[i][j], lo, hi);
                        float hv = fmaxf(lo + hi + b1j, 0.f);
                        part[i] = fmaf(hv, w2j, part[i]);
                    }
                }
#pragma unroll
                for (int i = 0; i < 4; i++) red[r0 + i][td] = part[i];
            }
            asm volatile("bar.sync 1, 256;" ::: "memory");
            if (t < 64) {
                float s = b2[0];
#pragma unroll
                for (int k = 0; k < 32; k++) s += red[t][k];
                g_buf[rb + t] = s;
            }
            asm volatile("bar.sync 1, 256;" ::: "memory");
        }
        // Release g_buf: arrive on grid barrier (wait comes after join).
        if (t == 0) {
            __threadfence();
            atomicAdd(&bar1, 1u);
        }
    } else {
        // ================= Screen group (threads 256..511) =================
        const int ts = t - 256;
        const int ns = ts >> 7;               // 0..1: 1024-pt slice
        const int vg = ts & 127;

        ull VX[4], VY[4], VZ[4];
#pragma unroll
        for (int q = 0; q < 4; q++) {
            const float* vp = verts + ((size_t)b * V_ + v0 + vg + q * 128) * 3;
            float x = -2.f * vp[0], y = -2.f * vp[1], z = -2.f * vp[2];
            VX[q] = pk2(x, x); VY[q] = pk2(y, y); VZ[q] = pk2(z, z);
        }

#pragma unroll
        for (int q = 0; q < 4; q++) { best[q] = INF; sec[q] = INF; sgpk[q] = 0; }

        // 32 segments of 32 points (16 pairs) within this 1024-pt slice
#pragma unroll 1
        for (int s = 0; s < 32; s++) {
            float mlo[4], mhi[4];
#pragma unroll
            for (int q = 0; q < 4; q++) { mlo[q] = INF; mhi[q] = INF; }
            const ulonglong2* base = (const ulonglong2*)&pts[(ns * 512 + s * 16) * 8];
#pragma unroll 4
            for (int k = 0; k < 16; k++) {
                ulonglong2 a  = base[2 * k];       // {x0,x1},{y0,y1}
                ulonglong2 bq = base[2 * k + 1];   // {z0,z1},{pp0,pp1}
#pragma unroll
                for (int q = 0; q < 4; q++) {
                    ull sc = ffma2(VZ[q], bq.x,
                              ffma2(VY[q], a.y,
                               ffma2(VX[q], a.x, bq.y)));
                    float lo, hi; upk2(sc, lo, hi);
                    mlo[q] = fminf(mlo[q], lo);
                    mhi[q] = fminf(mhi[q], hi);
                }
            }
#pragma unroll
            for (int q = 0; q < 4; q++) {
                float m = fminf(mlo[q], mhi[q]);
                int sp = sgpk[q];
                if (m < best[q]) {
                    sec[q] = best[q]; sgpk[q] = ((sp & 0xff) << 8) | s;
                    best[q] = m;
                } else if (m < sec[q]) {
                    sec[q] = m; sgpk[q] = (sp & 0xff) | (s << 8);
                }
            }
        }
    }

    // ---------------- Join: W region retires ----------------
    __syncthreads();

    if (w >= 8) {
        const int ts = t - 256;
        const int ns = ts >> 7;
        const int vg = ts & 127;
#pragma unroll
        for (int q = 0; q < 4; q++) {
            int vloc = vg + q * 128;
            int gA = ns * 32 + (sgpk[q] & 0xff);   // global segment 0..63
            int gB = ns * 32 + (sgpk[q] >> 8);
            cval[(ns * 2 + 0) * 512 + vloc] = best[q];
            cseg[(ns * 2 + 0) * 512 + vloc] = gA;
            cval[(ns * 2 + 1) * 512 + vloc] = sec[q];
            cseg[(ns * 2 + 1) * 512 + vloc] = gB;
        }
    }
    __syncthreads();

    // ---------------- Combine + exact rescan: ALL 512 threads ----------------
    int idx = 0;
    {
        float bv = INF, sv = INF;
        int bs = 64, ss = 64;
#pragma unroll
        for (int e = 0; e < 4; e++) {
            float val = cval[e * 512 + t];
            int   sg  = cseg[e * 512 + t];
            bool better = (val < bv) || (val == bv && sg < bs);
            if (better) {
                sv = bv; ss = bs; bv = val; bs = sg;
            } else if ((val < sv) || (val == sv && sg < ss)) {
                sv = val; ss = sg;
            }
        }

        const float* vp = verts + ((size_t)b * V_ + v0 + t) * 3;
        float vx = vp[0], vy = vp[1], vz = vp[2];
        float nvx = -2.f * vx, nvy = -2.f * vy, nvz = -2.f * vz;
        float vv = __fmaf_rn(vz, vz, __fmaf_rn(vy, vy, __fmul_rn(vx, vx)));

        int lo = min(bs, ss);
        int hi = max(bs, ss);
        float cur = INF;
#pragma unroll 1
        for (int pass = 0; pass < 2; pass++) {
            if (pass == 1 && hi == lo) break;
            int sb = (pass == 0 ? lo : hi) * 32;
            const ulonglong2* basep = (const ulonglong2*)&pts[(sb >> 1) * 8];
#pragma unroll 1
            for (int j = 0; j < 16; j++) {
                ulonglong2 A  = basep[2 * j];
                ulonglong2 Bq = basep[2 * j + 1];
                float x0, x1, y0, y1, z0, z1, w0, w1;
                upk2(A.x, x0, x1); upk2(A.y, y0, y1);
                upk2(Bq.x, z0, z1); upk2(Bq.y, w0, w1);
                float s2 = __fmaf_rn(nvz, z0, __fmaf_rn(nvy, y0, __fmul_rn(nvx, x0)));
                float d2 = __fadd_rn(__fadd_rn(vv, s2), w0);
                if (d2 < cur) { cur = d2; idx = sb + 2 * j; }
                float s3 = __fmaf_rn(nvz, z1, __fmaf_rn(nvy, y1, __fmul_rn(nvx, x1)));
                float d3 = __fadd_rn(__fadd_rn(vv, s3), w1);
                if (d3 < cur) { cur = d3; idx = sb + 2 * j + 1; }
            }
        }
    }

    // ---- Grid barrier WAIT (mostly hidden: arrive happened long ago) ----
    if (t == 0) {
        while (*(volatile unsigned int*)&bar1 < GRID_) __nanosleep(64);
    }
    __syncthreads();
    __threadfence();

    // ---- Gather ----
    out[b * V_ + v0 + t] = g_buf[b * N_ + idx];

    // ---------------- Exit: reset barrier (last block) ----------------
    __syncthreads();
    if (t == 0) {
        unsigned int r = atomicAdd(&bar_done, 1u);
        if (r == GRID_ - 1) {
            atomicExch(&bar1, 0u);
            atomicExch(&bar_done, 0u);
        }
    }
}

// =====================================================================
extern "C" void kernel_launch(void* const* d_in, const int* in_sizes, int n_in,
                              void* d_out, int out_size) {
    const float* verts = (const float*)d_in[0];   // [8,8192,3]
    const float* gpos  = (const float*)d_in[1];   // [8,2048,3]
    const float* proc  = (const float*)d_in[2];   // [8,2048,128]
    const float* W1    = (const float*)d_in[3];   // [128,128]
    const float* b1    = (const float*)d_in[4];   // [128]
    const float* W2    = (const float*)d_in[5];   // [128,1]
    const float* b2    = (const float*)d_in[6];   // [1]
    float* out = (float*)d_out;                   // [8,8192,1]

    cudaFuncSetAttribute(kernelFused, cudaFuncAttributeMaxDynamicSharedMemorySize,
                         96 * 1024);
    kernelFused<<<GRID_, THR_, 96 * 1024>>>(verts, gpos, proc, W1, b1, W2, b2, out);
}